// round 1
// baseline (speedup 1.0000x reference)
#include <cuda_runtime.h>
#include <cstdint>

#define NEGF (-1e30f)
#define CNUM 128
#define SMAX 401
#define NTHREADS 416

// Scratch: log-sum-exp per (b,t). B*T = 64*2000 = 128000 floats (512 KB).
__device__ float g_lse[64 * 2000];

// ---------------------------------------------------------------------------
// Kernel 1: per-row logsumexp over C=128 classes. One warp per (b,t) row.
// ---------------------------------------------------------------------------
__global__ void lse_kernel(const float* __restrict__ y, int rows) {
    int gw   = (blockIdx.x * blockDim.x + threadIdx.x) >> 5;
    int lane = threadIdx.x & 31;
    if (gw >= rows) return;
    float4 v = reinterpret_cast<const float4*>(y)[(size_t)gw * 32 + lane];
    float m = fmaxf(fmaxf(v.x, v.y), fmaxf(v.z, v.w));
#pragma unroll
    for (int o = 16; o; o >>= 1) m = fmaxf(m, __shfl_xor_sync(0xffffffffu, m, o));
    float s = __expf(v.x - m) + __expf(v.y - m) + __expf(v.z - m) + __expf(v.w - m);
#pragma unroll
    for (int o = 16; o; o >>= 1) s += __shfl_xor_sync(0xffffffffu, s, o);
    if (lane == 0) g_lse[gw] = m + __logf(s);
}

// ---------------------------------------------------------------------------
// Kernel 2: CTC alpha recursion. One CTA per batch element.
// Thread s (0..400) owns extended-lattice state s. Alpha double-buffered in
// shared with 2 leading NEG guard slots. y_pred rows streamed through an
// 8-stage shared ring filled by cp.async (issue distance 4).
// ---------------------------------------------------------------------------
__device__ __forceinline__ void cp_async16(uint32_t saddr, const void* g) {
    asm volatile("cp.async.cg.shared.global [%0], [%1], 16;" :: "r"(saddr), "l"(g));
}

__global__ __launch_bounds__(NTHREADS) void ctc_kernel(
    const float* __restrict__ y, const int* __restrict__ labels,
    const int* __restrict__ in_len, const int* __restrict__ lab_len,
    float* __restrict__ out, int T, int L)
{
    __shared__ float s_y[8][CNUM];        // 8-stage ring of raw y_pred rows
    __shared__ float s_al[2][SMAX + 2];   // alpha double buffer, +2 NEG guards

    const int b   = blockIdx.x;
    const int tid = threadIdx.x;
    const float* yb   = y + (size_t)b * T * CNUM;
    const float* lseb = g_lse + (size_t)b * T;
    const int ilen = in_len[b];

    // Per-thread static lattice info
    const int s = tid;
    int  ext_c = CNUM - 1;   // blank for even states
    bool skip  = false;
    if (s < SMAX && (s & 1)) {
        int l = s >> 1;
        int v = labels[b * L + l];
        ext_c = (v < 0) ? 0 : v;          // matches reference lab = where(y_true<0,0,y_true)
        if (s >= 3) {
            int v2 = labels[b * L + l - 1];
            v2 = (v2 < 0) ? 0 : v2;
            skip = (ext_c != v2);          // ext != blank always true for odd states
        }
    }

    if (tid < 2) { s_al[0][tid] = NEGF; s_al[1][tid] = NEGF; }

    const bool loader = (tid < 32);
    uint32_t smy = (uint32_t)__cvta_generic_to_shared(&s_y[0][0]);

    // Prologue: stages 0..3 in flight
    if (loader) {
#pragma unroll
        for (int d = 0; d < 4; ++d) {
            if (d < T) cp_async16(smy + (uint32_t)((d & 7) * CNUM + tid * 4) * 4,
                                  yb + (size_t)d * CNUM + tid * 4);
            asm volatile("cp.async.commit_group;");
        }
    }

    // t = 0 init
    if (loader) asm volatile("cp.async.wait_group 3;");
    __syncthreads();
    {
        float lse0 = lseb[0];
        if (s < SMAX) {
            float a = NEGF;
            if (s == 0)      a = s_y[0][CNUM - 1] - lse0;
            else if (s == 1) a = s_y[0][ext_c]    - lse0;
            s_al[0][s + 2] = a;
        }
        if (loader) {
            if (4 < T) cp_async16(smy + (uint32_t)((4 & 7) * CNUM + tid * 4) * 4,
                                  yb + (size_t)4 * CNUM + tid * 4);
            asm volatile("cp.async.commit_group;");
        }
    }

    // Main recursion: exactly one barrier per timestep.
    for (int t = 1; t < T; ++t) {
        if (loader) asm volatile("cp.async.wait_group 3;");
        __syncthreads();
        const int p = t & 1, q = p ^ 1;
        const int stage = t & 7;
        // Issue load for t+4 into stage (t+4)&7: last read 4 barriers ago -> safe.
        if (loader) {
            int tn = t + 4;
            if (tn < T) cp_async16(smy + (uint32_t)((tn & 7) * CNUM + tid * 4) * 4,
                                   yb + (size_t)tn * CNUM + tid * 4);
            asm volatile("cp.async.commit_group;");
        }
        if (s < SMAX) {
            float lset = lseb[t];                    // broadcast, L1-hit
            float a0 = s_al[q][s + 2];
            float a1 = s_al[q][s + 1];               // guard gives NEG at s=0
            float a2 = skip ? s_al[q][s] : NEGF;
            float m  = fmaxf(fmaxf(a0, a1), a2);
            float sum = __expf(a0 - m) + __expf(a1 - m) + __expf(a2 - m);
            float nw = m + __logf(sum) + (s_y[stage][ext_c] - lset);
            if (t >= ilen) nw = a0;                  // freeze past sequence end
            s_al[p][s + 2] = nw;
        }
    }

    __syncthreads();
    if (tid == 0) {
        int pf = (T - 1) & 1;
        int se = 2 * lab_len[b];
        float al = s_al[pf][se + 2];
        int sp = (se > 0) ? (se - 1) : 0;
        float ap = s_al[pf][sp + 2];
        float m = fmaxf(al, ap);
        out[b] = -(m + __logf(__expf(al - m) + __expf(ap - m)));
    }
}

// ---------------------------------------------------------------------------
extern "C" void kernel_launch(void* const* d_in, const int* in_sizes, int n_in,
                              void* d_out, int out_size) {
    const float* y  = (const float*)d_in[0];
    const int*   yt = (const int*)d_in[1];
    const int*   il = (const int*)d_in[2];
    const int*   ll = (const int*)d_in[3];
    int B = in_sizes[2];
    int L = in_sizes[1] / B;
    int rows = in_sizes[0] / CNUM;   // B*T
    int T = rows / B;

    int lse_blocks = (rows * 32 + 255) / 256;
    lse_kernel<<<lse_blocks, 256>>>(y, rows);
    ctc_kernel<<<B, NTHREADS>>>(y, yt, il, ll, (float*)d_out, T, L);
}

// round 3
// speedup vs baseline: 1.1750x; 1.1750x over previous
#include <cuda_runtime.h>
#include <cstdint>
#include <math.h>

#define CNUM 128
#define SMAX 401
#define NTHREADS 416
#define EFLOOR (-(1 << 28))

// Scratch: softmax(y_pred) rows, [B][T][C] = 64*2000*128 floats (64 MB).
__device__ float g_p[64 * 2000 * CNUM];

// ---------------------------------------------------------------------------
// Kernel 1: row softmax over C=128. One warp per (b,t) row.
// ---------------------------------------------------------------------------
__global__ void softmax_kernel(const float* __restrict__ y, int rows) {
    int gw   = (blockIdx.x * blockDim.x + threadIdx.x) >> 5;
    int lane = threadIdx.x & 31;
    if (gw >= rows) return;
    float4 v = reinterpret_cast<const float4*>(y)[(size_t)gw * 32 + lane];
    float m = fmaxf(fmaxf(v.x, v.y), fmaxf(v.z, v.w));
#pragma unroll
    for (int o = 16; o; o >>= 1) m = fmaxf(m, __shfl_xor_sync(0xffffffffu, m, o));
    float e0 = __expf(v.x - m), e1 = __expf(v.y - m);
    float e2 = __expf(v.z - m), e3 = __expf(v.w - m);
    float sm = e0 + e1 + e2 + e3;
#pragma unroll
    for (int o = 16; o; o >>= 1) sm += __shfl_xor_sync(0xffffffffu, sm, o);
    float inv = __frcp_rn(sm);
    float4 o4 = make_float4(e0 * inv, e1 * inv, e2 * inv, e3 * inv);
    reinterpret_cast<float4*>(g_p)[(size_t)gw * 32 + lane] = o4;
}

// ---------------------------------------------------------------------------
// Kernel 2: CTC alpha recursion in per-state extended-range linear domain.
// One CTA per batch element; thread s owns lattice state s.
// alpha[s] = (mantissa float in [1,2) or 0, exponent int) packed in int2:
//   .x = float bits of mantissa, .y = exponent (EFLOOR for zero).
// Recursion: align neighbor mantissas by exact powers of 2 (bit-constructed),
// FMA-sum, multiply by softmax prob, repack via bit ops. No MUFU, no F2I/I2F.
// Softmax rows streamed through an 8-stage shared ring via cp.async.
// ---------------------------------------------------------------------------
__device__ __forceinline__ void cp_async16(uint32_t saddr, const void* g) {
    asm volatile("cp.async.cg.shared.global [%0], [%1], 16;" :: "r"(saddr), "l"(g));
}

__global__ __launch_bounds__(NTHREADS) void ctc_kernel(
    const int* __restrict__ labels, const int* __restrict__ in_len,
    const int* __restrict__ lab_len, float* __restrict__ out, int T, int L)
{
    __shared__ float s_y[8][CNUM];         // ring of softmax rows
    __shared__ int2  s_al[2][SMAX + 2];    // alpha double buffer, +2 guards

    const int b    = blockIdx.x;
    const int tid  = threadIdx.x;
    const int lane = tid & 31;
    const float* pb = g_p + (size_t)b * T * CNUM;
    const int tend  = min(T, in_len[b]);

    // Per-thread static lattice info
    const int s = tid;
    int  ext_c = CNUM - 1;            // blank for even states
    bool skip  = false;
    if (s < SMAX && (s & 1)) {
        int v = labels[b * L + (s >> 1)];
        ext_c = (v < 0) ? 0 : v;      // ref: lab = where(y_true<0, 0, y_true)
        if (s >= 3) {
            int v2 = labels[b * L + (s >> 1) - 1];
            v2 = (v2 < 0) ? 0 : v2;
            skip = (ext_c != v2);
        }
    }

    // Guard slots (never rewritten)
    if (tid < 2) {
        s_al[0][tid] = make_int2(0, EFLOOR);
        s_al[1][tid] = make_int2(0, EFLOOR);
    }

    const bool loader = (tid < 32);
    uint32_t smy = (uint32_t)__cvta_generic_to_shared(&s_y[0][0]);

    // Prologue: stages 0..3 in flight
    if (loader) {
#pragma unroll
        for (int d = 0; d < 4; ++d) {
            if (d < T) cp_async16(smy + (uint32_t)((d & 7) * CNUM + lane * 4) * 4,
                                  pb + (size_t)d * CNUM + lane * 4);
            asm volatile("cp.async.commit_group;");
        }
        asm volatile("cp.async.wait_group 3;");
    }
    __syncthreads();

    // t = 0 init
    if (s < SMAX) {
        int2 R = make_int2(0, EFLOOR);
        if (s < 2) {
            float v = (s == 0) ? s_y[0][CNUM - 1] : s_y[0][ext_c];  // > 0
            int bits = __float_as_int(v);
            R.x = (bits & 0x007FFFFF) | 0x3F800000;
            R.y = (bits >> 23) - 127;
        }
        s_al[0][s + 2] = R;
    }
    if (loader) {
        if (4 < T) cp_async16(smy + (uint32_t)(4 * CNUM + lane * 4) * 4,
                              pb + (size_t)4 * CNUM + lane * 4);
        asm volatile("cp.async.commit_group;");
    }

    auto step = [&](int t, int stage, int par) {
        if (loader) asm volatile("cp.async.wait_group 3;");
        __syncthreads();
        const int q = par ^ 1;
        if (loader) {
            int tn = t + 4;
            if (tn < T) cp_async16(smy + (uint32_t)((tn & 7) * CNUM + lane * 4) * 4,
                                   pb + (size_t)tn * CNUM + lane * 4);
            asm volatile("cp.async.commit_group;");
        }
        if (s < SMAX) {
            int2 A0 = s_al[q][s + 2];
            int2 A1 = s_al[q][s + 1];     // guard -> (0, EFLOOR) at s=0
            int2 A2 = s_al[q][s];
            int   e2 = skip ? A2.y : EFLOOR;
            float m2 = skip ? __int_as_float(A2.x) : 0.f;
            int em = max(A0.y, max(A1.y, e2));
            int c  = 127 - em;
            float f0 = __int_as_float(max(A0.y + c, 0) << 23);  // exact 2^(e0-em)
            float f1 = __int_as_float(max(A1.y + c, 0) << 23);
            float f2 = __int_as_float(max(e2  + c, 0) << 23);
            float sum = __int_as_float(A0.x) * f0
                      + __int_as_float(A1.x) * f1
                      + m2 * f2;
            float v = sum * s_y[stage][ext_c];
            int bits = __float_as_int(v);     // v >= 0
            bool z = (v == 0.f);
            int2 R;
            R.x = z ? 0      : ((bits & 0x007FFFFF) | 0x3F800000);
            R.y = z ? EFLOOR : ((bits >> 23) - c);
            s_al[par][s + 2] = R;
        }
    };

    int t = 1;
    for (; t < tend && (t & 7); ++t)
        step(t, t & 7, t & 1);
    for (; t + 8 <= tend; t += 8) {
#pragma unroll
        for (int u = 0; u < 8; ++u)
            step(t + u, u, u & 1);
    }
    for (; t < tend; ++t)
        step(t, t & 7, t & 1);

    __syncthreads();
    if (tid == 0) {
        int pf = (tend - 1) & 1;
        int se = 2 * lab_len[b];
        int sp = (se > 0) ? (se - 1) : 0;
        int2 Al = s_al[pf][se + 2];
        int2 Ap = s_al[pf][sp + 2];
        double el = (double)Al.y, ep = (double)Ap.y;
        double em = fmax(el, ep);
        double dl = fmax(el - em, -1100.0);
        double dp = fmax(ep - em, -1100.0);
        double val = (double)__int_as_float(Al.x) * exp2(dl)
                   + (double)__int_as_float(Ap.x) * exp2(dp);
        out[b] = (float)(-(log(val) + em * 0.6931471805599453));
    }
}

// ---------------------------------------------------------------------------
extern "C" void kernel_launch(void* const* d_in, const int* in_sizes, int n_in,
                              void* d_out, int out_size) {
    const float* y  = (const float*)d_in[0];
    const int*   yt = (const int*)d_in[1];
    const int*   il = (const int*)d_in[2];
    const int*   ll = (const int*)d_in[3];
    int B = in_sizes[2];
    int L = in_sizes[1] / B;
    int rows = in_sizes[0] / CNUM;   // B*T
    int T = rows / B;

    int sm_blocks = (rows * 32 + 255) / 256;
    softmax_kernel<<<sm_blocks, 256>>>(y, rows);
    ctc_kernel<<<B, NTHREADS>>>(yt, il, ll, (float*)d_out, T, L);
}